// round 8
// baseline (speedup 1.0000x reference)
#include <cuda_runtime.h>
#include <cuda_bf16.h>
#include <math.h>

// ---------------- scratch (static device globals; no allocation) ----------------
__device__ float g_lbuf[256 * 22 * 4096];   // log-eig planes, layout [n][ch][pos]
__device__ float g_h2[256 * 32 * 4096];     // h2, layout [n][ch][pos]
__device__ float g_eusum[256 * 22];
__device__ float g_eusq[256 * 22];
__device__ float g_h2sum[256 * 32];
__device__ float g_h2sq[256 * 32];
__device__ float g_cov3[256 * 32];
__device__ float g_em3[10];

#define MAXSWEEPS 10
#define UPAD 66   // column stride (floats); even -> float2-aligned

// round-robin pairing: round r in [0,63), pair k in [0,32)
__device__ __forceinline__ void pairpq(int r, int k, int& p, int& q) {
    if (k == 0) { p = 63; q = r; }
    else {
        p = r + k; if (p >= 63) p -= 63;
        q = r - k; if (q < 0)  q += 63;
    }
}

// ---------------- K0: init accumulators + scalar-embedding MLP ----------------
__global__ void init_kernel(const void* __restrict__ Mraw,
                            const float* __restrict__ we1, const float* __restrict__ be1,
                            const float* __restrict__ we2, const float* __restrict__ be2,
                            const float* __restrict__ we3, const float* __restrict__ be3,
                            const float* __restrict__ ln_g, const float* __restrict__ ln_b) {
    const int t = threadIdx.x;  // 256 threads, 1 block
    for (int i = t; i < 256 * 32; i += 256) {
        g_h2sum[i] = 0.f; g_h2sq[i] = 0.f; g_cov3[i] = 0.f;
    }
    __shared__ float md[2];
    __shared__ float em[10], emln[10], em2[100];
    __shared__ float mu_s, isd_s;
    if (t == 0) {
        int mi = *(const int*)Mraw;
        float Mv = (mi > 0 && mi < 100000000) ? (float)mi : __int_as_float(mi);
        md[0] = Mv / 500.0f;
        md[1] = 64.0f / 100.0f;
    }
    __syncthreads();
    if (t < 10) em[t] = md[0] * we1[t] + md[1] * we1[10 + t] + be1[t];
    __syncthreads();
    if (t == 0) {
        float s = 0.f, s2 = 0.f;
        for (int j = 0; j < 10; ++j) { s += em[j]; s2 += em[j] * em[j]; }
        float mu = s * 0.1f;
        float var = fmaxf(s2 * 0.1f - mu * mu, 0.f);
        mu_s = mu;
        isd_s = rsqrtf(var + 1e-3f);   // keras LN: eps inside sqrt
    }
    __syncthreads();
    if (t < 10) emln[t] = (em[t] - mu_s) * isd_s * ln_g[t] + ln_b[t];
    __syncthreads();
    if (t < 100) {
        float a = be2[t];
        for (int j = 0; j < 10; ++j) a += emln[j] * we2[j * 100 + t];
        em2[t] = fmaxf(a, 0.f);
    }
    __syncthreads();
    if (t < 10) {
        float a = be3[t];
        for (int k = 0; k < 100; ++k) a += em2[k] * we3[k * 10 + t];
        g_em3[t] = em[t] + a;
    }
}

// ---------------- K1: shifted one-sided (Hestenes) Jacobi + log reconstruction ----
// U = A + sigma*I (PD, sigma = ||A||_F), V = I, column-major (stride UPAD).
// Per round each warp owns 4 disjoint pairs: dot products for all 4 pairs are
// computed first and their shuffle butterflies interleaved (4-way ILP on the
// 26-cyc SHFL latency), column sq-norms are maintained incrementally in smem
// (kills the second butterfly). 1 __syncthreads per round.
__global__ __launch_bounds__(256, 5) void eig_kernel(const float* __restrict__ x) {
    __shared__ __align__(16) float U[64 * UPAD];
    __shared__ __align__(16) float V[64 * UPAD];
    __shared__ float nrm[64];
    __shared__ float fv[64];
    __shared__ float wred[16];
    __shared__ float sig_s, sig2_s;
    __shared__ int conv_s;

    const int t = threadIdx.x;
    const int warp = t >> 5, lane = t & 31;
    const int b = blockIdx.x;      // n*22 + ch
    const float* src = x + (size_t)b * 4096;

    // load plane (coalesced) into U, V = I
    #pragma unroll
    for (int it = 0; it < 16; ++it) {
        int id = t + 256 * it;
        int r_ = id >> 6, c_ = id & 63;
        U[c_ * UPAD + r_] = src[id];
        V[c_ * UPAD + r_] = (r_ == c_) ? 1.f : 0.f;
    }
    __syncthreads();
    // symmetrize in smem + Frobenius norm^2
    float fn = 0.f;
    #pragma unroll
    for (int it = 0; it < 16; ++it) {
        int id = t + 256 * it;
        int i = id >> 6, j = id & 63;
        if (i < j) {
            float a = 0.5f * (U[i * UPAD + j] + U[j * UPAD + i]);
            U[i * UPAD + j] = a; U[j * UPAD + i] = a;
            fn += 2.f * a * a;
        } else if (i == j) {
            float d = U[i * UPAD + i];
            fn += d * d;
        }
    }
    #pragma unroll
    for (int off = 16; off; off >>= 1) fn += __shfl_xor_sync(0xffffffffu, fn, off);
    if (lane == 0) wred[warp] = fn;
    __syncthreads();
    if (t == 0) {
        float s = 0.f;
        for (int i = 0; i < 8; ++i) s += wred[i];
        sig2_s = s;
        sig_s = sqrtf(s);
        conv_s = 0;
    }
    __syncthreads();
    const float sigma = sig_s;
    if (t < 64) U[t * UPAD + t] += sigma;   // shift: U = A + sigma*I  (PD)
    __syncthreads();
    // initial column sq-norms: warp w, lanes cover 8 columns x 8 rows... simpler:
    // each of first 64 threads reduces its column (broadcast-ish LDS, one-time).
    if (t < 64) {
        const float* uc = U + t * UPAD;
        float s = 0.f;
        #pragma unroll 8
        for (int r_ = 0; r_ < 64; ++r_) { float v = uc[r_]; s += v * v; }
        nrm[t] = s;
    }
    __syncthreads();

    const float skipthr = 1e-5f * sig2_s + 1e-30f;
    const float convthr = 1e-4f * sig2_s + 1e-30f;

    for (int sweep = 0; sweep < MAXSWEEPS; ++sweep) {
        float swmax = 0.f;
        for (int r = 0; r < 63; ++r) {
            // ---- phase A: dots for all 4 pairs (disjoint columns), ILP'd butterflies
            float2 up0, uq0, up1, uq1, up2, uq2, up3, uq3;
            float spq[4];
            {
                int p, q;
                pairpq(r, (warp << 2) | 0, p, q);
                up0 = ((float2*)(U + p * UPAD))[lane]; uq0 = ((float2*)(U + q * UPAD))[lane];
                spq[0] = up0.x * uq0.x + up0.y * uq0.y;
                pairpq(r, (warp << 2) | 1, p, q);
                up1 = ((float2*)(U + p * UPAD))[lane]; uq1 = ((float2*)(U + q * UPAD))[lane];
                spq[1] = up1.x * uq1.x + up1.y * uq1.y;
                pairpq(r, (warp << 2) | 2, p, q);
                up2 = ((float2*)(U + p * UPAD))[lane]; uq2 = ((float2*)(U + q * UPAD))[lane];
                spq[2] = up2.x * uq2.x + up2.y * uq2.y;
                pairpq(r, (warp << 2) | 3, p, q);
                up3 = ((float2*)(U + p * UPAD))[lane]; uq3 = ((float2*)(U + q * UPAD))[lane];
                spq[3] = up3.x * uq3.x + up3.y * uq3.y;
            }
            #pragma unroll
            for (int off = 16; off; off >>= 1) {
                spq[0] += __shfl_xor_sync(0xffffffffu, spq[0], off);
                spq[1] += __shfl_xor_sync(0xffffffffu, spq[1], off);
                spq[2] += __shfl_xor_sync(0xffffffffu, spq[2], off);
                spq[3] += __shfl_xor_sync(0xffffffffu, spq[3], off);
            }
            // ---- phase B: apply rotations (per pair; U regs already held)
            #pragma unroll
            for (int j = 0; j < 4; ++j) {
                float sp = spq[j];
                swmax = fmaxf(swmax, fabsf(sp));
                if (fabsf(sp) > skipthr) {
                    int p, q; pairpq(r, (warp << 2) | j, p, q);
                    float dpp = nrm[p], dqq = nrm[q];    // broadcast LDS
                    float tau = (dqq - dpp) / (2.f * sp);
                    float tt = copysignf(1.f, tau) / (fabsf(tau) + sqrtf(1.f + tau * tau));
                    float c = rsqrtf(1.f + tt * tt);
                    float s = tt * c;
                    float2 up = (j == 0) ? up0 : (j == 1) ? up1 : (j == 2) ? up2 : up3;
                    float2 uq = (j == 0) ? uq0 : (j == 1) ? uq1 : (j == 2) ? uq2 : uq3;
                    float2 np, nq;
                    np.x = c * up.x - s * uq.x;  np.y = c * up.y - s * uq.y;
                    nq.x = s * up.x + c * uq.x;  nq.y = s * up.y + c * uq.y;
                    ((float2*)(U + p * UPAD))[lane] = np;
                    ((float2*)(U + q * UPAD))[lane] = nq;
                    float2* Vp = (float2*)(V + p * UPAD);
                    float2* Vq = (float2*)(V + q * UPAD);
                    float2 vp = Vp[lane], vq = Vq[lane];
                    float2 wp, wq;
                    wp.x = c * vp.x - s * vq.x;  wp.y = c * vp.y - s * vq.y;
                    wq.x = s * vp.x + c * vq.x;  wq.y = s * vp.y + c * vq.y;
                    Vp[lane] = wp; Vq[lane] = wq;
                    if (lane == 0) {
                        float cc = c * c, ss = s * s, cs2 = 2.f * c * s * sp;
                        nrm[p] = cc * dpp + ss * dqq - cs2;
                        nrm[q] = ss * dpp + cc * dqq + cs2;
                    }
                }
            }
            __syncthreads();
        }
        // convergence check (swmax warp-uniform after butterfly)
        if (lane == 0) wred[warp] = swmax;
        __syncthreads();
        if (t == 0) {
            float m = wred[0];
            for (int i = 1; i < 8; ++i) m = fmaxf(m, wred[i]);
            conv_s = (m < convthr) ? 1 : 0;
        }
        __syncthreads();
        if (conv_s) break;
    }

    // lambda_c = u_c . v_c - sigma  (double to dodge shift cancellation), f(lambda)
    if (t < 64) {
        double acc = 0.0;
        const float* uc = U + t * UPAD;
        const float* vc = V + t * UPAD;
        #pragma unroll 8
        for (int r_ = 0; r_ < 64; ++r_) acc += (double)uc[r_] * (double)vc[r_];
        float lam = (float)(acc - (double)sigma);
        fv[t] = logf(fmaxf(lam, 1e-4f));
    }
    __syncthreads();
    // U[m][i] := V[m][i] * fv[m]
    #pragma unroll
    for (int it = 0; it < 16; ++it) {
        int id = t + 256 * it;
        int m = id >> 6, i = id & 63;
        U[m * UPAD + i] = V[m * UPAD + i] * fv[m];
    }
    __syncthreads();
    // L[i][j] = sum_m U[m][i] * V[m][j]; thread: row i0 x 16-col chunk
    const int i0 = t >> 2;
    const int j0 = (t & 3) << 4;
    float acc16[16];
    #pragma unroll
    for (int jj = 0; jj < 16; ++jj) acc16[jj] = 0.f;
    #pragma unroll 4
    for (int m = 0; m < 64; ++m) {
        float a = U[m * UPAD + i0];
        const float* vr = V + m * UPAD + j0;
        #pragma unroll
        for (int jj = 0; jj < 16; ++jj) acc16[jj] += a * vr[jj];
    }
    float lsum = 0.f, lsq = 0.f;
    float* dst = g_lbuf + (size_t)b * 4096;
    #pragma unroll
    for (int jj = 0; jj < 16; ++jj) {
        float v = acc16[jj];
        dst[i0 * 64 + j0 + jj] = v;
        lsum += v; lsq += v * v;
    }
    #pragma unroll
    for (int off = 16; off; off >>= 1) {
        lsum += __shfl_down_sync(0xffffffffu, lsum, off);
        lsq  += __shfl_down_sync(0xffffffffu, lsq, off);
    }
    if (lane == 0) { wred[warp] = lsum; wred[8 + warp] = lsq; }
    __syncthreads();
    if (t == 0) {
        float s1 = 0.f, s2 = 0.f;
        for (int i = 0; i < 8; ++i) { s1 += wred[i]; s2 += wred[8 + i]; }
        g_eusum[b] = s1;
        g_eusq[b]  = s2;
    }
}

// ---------------- K2: block 1  (matnorm(eu) @ w2 -> relu -> @w3 + eu) ----------------
__global__ __launch_bounds__(128) void dense1_kernel(const float* __restrict__ w2, const float* __restrict__ b2,
                                                     const float* __restrict__ w3, const float* __restrict__ b3) {
    const int t = threadIdx.x;
    const int n = blockIdx.y;
    const int pos = blockIdx.x * 128 + t;
    __shared__ float sw2[1024], sw3[1024], sb2[32], sb3[32];
    __shared__ float meanS[22], isdS[22], em3S[10];
    __shared__ float acc1[32], acc2[32];
    for (int i = t; i < 1024; i += 128) { sw2[i] = w2[i]; sw3[i] = w3[i]; }
    if (t < 32) { sb2[t] = b2[t]; sb3[t] = b3[t]; acc1[t] = 0.f; acc2[t] = 0.f; }
    if (t < 22) {
        float mu = g_eusum[n * 22 + t] * (1.f / 4096.f);
        float var = fmaxf(g_eusq[n * 22 + t] * (1.f / 4096.f) - mu * mu, 0.f);
        meanS[t] = mu;
        isdS[t] = 1.f / fmaxf(sqrtf(var), 1e-3f);   // matnorm: clamp OUTSIDE sqrt
    }
    if (t < 10) em3S[t] = g_em3[t];
    __syncthreads();

    float eu[32];
    #pragma unroll
    for (int c = 0; c < 22; ++c) eu[c] = g_lbuf[((size_t)n * 22 + c) * 4096 + pos];
    #pragma unroll
    for (int c = 22; c < 32; ++c) eu[c] = em3S[c - 22];
    float mt[22];
    #pragma unroll
    for (int c = 0; c < 22; ++c) mt[c] = (eu[c] - meanS[c]) * isdS[c];
    // matnorm of the constant embedding channels is exactly 0 (std clamped), so skip c>=22
    float res[32];
    #pragma unroll
    for (int o = 0; o < 32; ++o) {
        float a = sb2[o];
        #pragma unroll
        for (int c = 0; c < 22; ++c) a += mt[c] * sw2[c * 32 + o];
        res[o] = fmaxf(a, 0.f);
    }
    #pragma unroll
    for (int o = 0; o < 32; ++o) {
        float a = sb3[o];
        #pragma unroll
        for (int c = 0; c < 32; ++c) a += res[c] * sw3[c * 32 + o];
        float h = eu[o] + a;
        g_h2[((size_t)n * 32 + o) * 4096 + pos] = h;
        float s1 = h, s2 = h * h;
        #pragma unroll
        for (int off = 16; off; off >>= 1) {
            s1 += __shfl_down_sync(0xffffffffu, s1, off);
            s2 += __shfl_down_sync(0xffffffffu, s2, off);
        }
        if ((t & 31) == 0) { atomicAdd(&acc1[o], s1); atomicAdd(&acc2[o], s2); }
    }
    __syncthreads();
    if (t < 32) {
        atomicAdd(&g_h2sum[n * 32 + t], acc1[t]);
        atomicAdd(&g_h2sq[n * 32 + t], acc2[t]);
    }
}

// ---------------- K3: block 2  (matnorm(h2) @ w4 -> relu -> @w5 + h2, mean) ----------------
__global__ __launch_bounds__(128) void dense2_kernel(const float* __restrict__ w4, const float* __restrict__ b4,
                                                     const float* __restrict__ w5, const float* __restrict__ b5) {
    const int t = threadIdx.x;
    const int n = blockIdx.y;
    const int pos = blockIdx.x * 128 + t;
    __shared__ float sw4[1024], sw5[1024], sb4[32], sb5[32];
    __shared__ float meanS[32], isdS[32];
    __shared__ float acc1[32];
    for (int i = t; i < 1024; i += 128) { sw4[i] = w4[i]; sw5[i] = w5[i]; }
    if (t < 32) {
        sb4[t] = b4[t]; sb5[t] = b5[t]; acc1[t] = 0.f;
        float mu = g_h2sum[n * 32 + t] * (1.f / 4096.f);
        float var = fmaxf(g_h2sq[n * 32 + t] * (1.f / 4096.f) - mu * mu, 0.f);
        meanS[t] = mu;
        isdS[t] = 1.f / fmaxf(sqrtf(var), 1e-3f);
    }
    __syncthreads();

    float hv[32];
    #pragma unroll
    for (int c = 0; c < 32; ++c) hv[c] = g_h2[((size_t)n * 32 + c) * 4096 + pos];
    float mt[32];
    #pragma unroll
    for (int c = 0; c < 32; ++c) mt[c] = (hv[c] - meanS[c]) * isdS[c];
    float res[32];
    #pragma unroll
    for (int o = 0; o < 32; ++o) {
        float a = sb4[o];
        #pragma unroll
        for (int c = 0; c < 32; ++c) a += mt[c] * sw4[c * 32 + o];
        res[o] = fmaxf(a, 0.f);
    }
    #pragma unroll
    for (int o = 0; o < 32; ++o) {
        float a = sb5[o];
        #pragma unroll
        for (int c = 0; c < 32; ++c) a += res[c] * sw5[c * 32 + o];
        float h = hv[o] + a;
        float s1 = h;
        #pragma unroll
        for (int off = 16; off; off >>= 1) s1 += __shfl_down_sync(0xffffffffu, s1, off);
        if ((t & 31) == 0) atomicAdd(&acc1[o], s1);
    }
    __syncthreads();
    if (t < 32) atomicAdd(&g_cov3[n * 32 + t], acc1[t]);
}

// ---------------- K4: head (cov3 @ w -> softmax) ----------------
__global__ void head_kernel(const float* __restrict__ w, float* __restrict__ out) {
    const int n = threadIdx.x;  // 256 threads
    float c[32];
    #pragma unroll
    for (int ch = 0; ch < 32; ++ch) c[ch] = g_cov3[n * 32 + ch] * (1.f / 4096.f);
    float lg[7];
    #pragma unroll
    for (int cls = 0; cls < 7; ++cls) {
        float a = 0.f;
        #pragma unroll
        for (int ch = 0; ch < 32; ++ch) a += c[ch] * w[ch * 7 + cls];
        lg[cls] = a;
    }
    float mx = lg[0];
    #pragma unroll
    for (int cls = 1; cls < 7; ++cls) mx = fmaxf(mx, lg[cls]);
    float sum = 0.f;
    #pragma unroll
    for (int cls = 0; cls < 7; ++cls) { lg[cls] = expf(lg[cls] - mx); sum += lg[cls]; }
    float inv = 1.f / sum;
    #pragma unroll
    for (int cls = 0; cls < 7; ++cls) out[n * 7 + cls] = lg[cls] * inv;
}

// ---------------- launch ----------------
extern "C" void kernel_launch(void* const* d_in, const int* in_sizes, int n_in,
                              void* d_out, int out_size) {
    const float* x   = (const float*)d_in[0];
    const void*  M   = d_in[1];
    const float* w   = (const float*)d_in[2];
    const float* w2  = (const float*)d_in[3];
    const float* b2  = (const float*)d_in[4];
    const float* w3  = (const float*)d_in[5];
    const float* b3  = (const float*)d_in[6];
    const float* w4  = (const float*)d_in[7];
    const float* b4  = (const float*)d_in[8];
    const float* w5  = (const float*)d_in[9];
    const float* b5  = (const float*)d_in[10];
    const float* we1 = (const float*)d_in[11];
    const float* be1 = (const float*)d_in[12];
    const float* we2 = (const float*)d_in[13];
    const float* be2 = (const float*)d_in[14];
    const float* we3 = (const float*)d_in[15];
    const float* be3 = (const float*)d_in[16];
    const float* lng = (const float*)d_in[17];
    const float* lnb = (const float*)d_in[18];

    init_kernel<<<1, 256>>>(M, we1, be1, we2, be2, we3, be3, lng, lnb);
    eig_kernel<<<256 * 22, 256>>>(x);
    dense1_kernel<<<dim3(32, 256), 128>>>(w2, b2, w3, b3);
    dense2_kernel<<<dim3(32, 256), 128>>>(w4, b4, w5, b5);
    head_kernel<<<1, 256>>>(w, (float*)d_out);
}

// round 9
// speedup vs baseline: 1.2328x; 1.2328x over previous
#include <cuda_runtime.h>
#include <cuda_bf16.h>
#include <math.h>

// ---------------- scratch (static device globals; no allocation) ----------------
__device__ float g_lbuf[256 * 22 * 4096];   // log-eig planes, layout [n][ch][pos]
__device__ float g_h2[256 * 32 * 4096];     // h2, layout [n][ch][pos]
__device__ float g_eusum[256 * 22];
__device__ float g_eusq[256 * 22];
__device__ float g_h2sum[256 * 32];
__device__ float g_h2sq[256 * 32];
__device__ float g_cov3[256 * 32];
__device__ float g_em3[10];

#define MAXSWEEPS 10
#define UPAD 66   // column stride (floats); even -> float2-aligned

// round-robin pairing: round r in [0,63), pair k in [0,32)
__device__ __forceinline__ void pairpq(int r, int k, int& p, int& q) {
    if (k == 0) { p = 63; q = r; }
    else {
        p = r + k; if (p >= 63) p -= 63;
        q = r - k; if (q < 0)  q += 63;
    }
}

// ---------------- K0: init accumulators + scalar-embedding MLP ----------------
__global__ void init_kernel(const void* __restrict__ Mraw,
                            const float* __restrict__ we1, const float* __restrict__ be1,
                            const float* __restrict__ we2, const float* __restrict__ be2,
                            const float* __restrict__ we3, const float* __restrict__ be3,
                            const float* __restrict__ ln_g, const float* __restrict__ ln_b) {
    const int t = threadIdx.x;  // 256 threads, 1 block
    for (int i = t; i < 256 * 32; i += 256) {
        g_h2sum[i] = 0.f; g_h2sq[i] = 0.f; g_cov3[i] = 0.f;
    }
    __shared__ float md[2];
    __shared__ float em[10], emln[10], em2[100];
    __shared__ float mu_s, isd_s;
    if (t == 0) {
        int mi = *(const int*)Mraw;
        float Mv = (mi > 0 && mi < 100000000) ? (float)mi : __int_as_float(mi);
        md[0] = Mv / 500.0f;
        md[1] = 64.0f / 100.0f;
    }
    __syncthreads();
    if (t < 10) em[t] = md[0] * we1[t] + md[1] * we1[10 + t] + be1[t];
    __syncthreads();
    if (t == 0) {
        float s = 0.f, s2 = 0.f;
        for (int j = 0; j < 10; ++j) { s += em[j]; s2 += em[j] * em[j]; }
        float mu = s * 0.1f;
        float var = fmaxf(s2 * 0.1f - mu * mu, 0.f);
        mu_s = mu;
        isd_s = rsqrtf(var + 1e-3f);   // keras LN: eps inside sqrt
    }
    __syncthreads();
    if (t < 10) emln[t] = (em[t] - mu_s) * isd_s * ln_g[t] + ln_b[t];
    __syncthreads();
    if (t < 100) {
        float a = be2[t];
        for (int j = 0; j < 10; ++j) a += emln[j] * we2[j * 100 + t];
        em2[t] = fmaxf(a, 0.f);
    }
    __syncthreads();
    if (t < 10) {
        float a = be3[t];
        for (int k = 0; k < 100; ++k) a += em2[k] * we3[k * 10 + t];
        g_em3[t] = em[t] + a;
    }
}

// ---------------- K1: shifted one-sided Jacobi WITHOUT accumulated V ----------
// U = A + sigma*I (PD, sigma = ||A||_F), column-major (stride UPAD).
// At convergence the columns of U are rho_c * w_c where w_c are the
// eigenvectors of A and rho_c = lambda_c + sigma (symmetric PD => left
// singular vectors == eigenvectors). So no V is needed:
//   lambda_c = ||u_c|| - sigma,   L = sum_c (f_c/||u_c||^2) u_c u_c^T.
// Column sq-norms maintained incrementally in nrm[] (exact update), final
// norms recomputed exactly in double. 1 __syncthreads per round.
__global__ __launch_bounds__(256, 5) void eig_kernel(const float* __restrict__ x) {
    __shared__ __align__(16) float U[64 * UPAD];
    __shared__ float nrm[64];
    __shared__ float gsc[64];
    __shared__ float wred[16];
    __shared__ float sig_s, sig2_s;
    __shared__ int conv_s;

    const int t = threadIdx.x;
    const int warp = t >> 5, lane = t & 31;
    const int b = blockIdx.x;      // n*22 + ch
    const float* src = x + (size_t)b * 4096;

    // load plane (coalesced) into U column-major
    #pragma unroll
    for (int it = 0; it < 16; ++it) {
        int id = t + 256 * it;
        int r_ = id >> 6, c_ = id & 63;
        U[c_ * UPAD + r_] = src[id];
    }
    __syncthreads();
    // symmetrize in smem + Frobenius norm^2
    float fn = 0.f;
    #pragma unroll
    for (int it = 0; it < 16; ++it) {
        int id = t + 256 * it;
        int i = id >> 6, j = id & 63;
        if (i < j) {
            float a = 0.5f * (U[i * UPAD + j] + U[j * UPAD + i]);
            U[i * UPAD + j] = a; U[j * UPAD + i] = a;
            fn += 2.f * a * a;
        } else if (i == j) {
            float d = U[i * UPAD + i];
            fn += d * d;
        }
    }
    #pragma unroll
    for (int off = 16; off; off >>= 1) fn += __shfl_xor_sync(0xffffffffu, fn, off);
    if (lane == 0) wred[warp] = fn;
    __syncthreads();
    if (t == 0) {
        float s = 0.f;
        for (int i = 0; i < 8; ++i) s += wred[i];
        sig2_s = s;
        sig_s = sqrtf(s);
        conv_s = 0;
    }
    __syncthreads();
    const float sigma = sig_s;
    if (t < 64) U[t * UPAD + t] += sigma;   // shift: U = A + sigma*I  (PD)
    __syncthreads();
    // initial column sq-norms (one-time)
    if (t < 64) {
        const float* uc = U + t * UPAD;
        float s = 0.f;
        #pragma unroll 8
        for (int r_ = 0; r_ < 64; ++r_) { float v = uc[r_]; s += v * v; }
        nrm[t] = s;
    }
    __syncthreads();

    const float skipthr = 1e-5f * sig2_s + 1e-30f;
    const float convthr = 1e-4f * sig2_s + 1e-30f;

    for (int sweep = 0; sweep < MAXSWEEPS; ++sweep) {
        float swmax = 0.f;
        for (int r = 0; r < 63; ++r) {
            #pragma unroll
            for (int j = 0; j < 4; ++j) {
                int k = (warp << 2) | j;
                int p, q; pairpq(r, k, p, q);
                float2* Up = (float2*)(U + p * UPAD);
                float2* Uq = (float2*)(U + q * UPAD);
                float2 up = Up[lane], uq = Uq[lane];
                float spq = up.x * uq.x + up.y * uq.y;
                #pragma unroll
                for (int off = 16; off; off >>= 1)
                    spq += __shfl_xor_sync(0xffffffffu, spq, off);
                swmax = fmaxf(swmax, fabsf(spq));
                if (fabsf(spq) > skipthr) {
                    float dpp = nrm[p], dqq = nrm[q];    // broadcast LDS
                    float tau = (dqq - dpp) / (2.f * spq);
                    float tt = copysignf(1.f, tau) / (fabsf(tau) + sqrtf(1.f + tau * tau));
                    float c = rsqrtf(1.f + tt * tt);
                    float s = tt * c;
                    float2 np, nq;
                    np.x = c * up.x - s * uq.x;  np.y = c * up.y - s * uq.y;
                    nq.x = s * up.x + c * uq.x;  nq.y = s * up.y + c * uq.y;
                    Up[lane] = np; Uq[lane] = nq;
                    if (lane == 0) {
                        float cc = c * c, ss = s * s, cs2 = 2.f * c * s * spq;
                        nrm[p] = cc * dpp + ss * dqq - cs2;
                        nrm[q] = ss * dpp + cc * dqq + cs2;
                    }
                }
            }
            __syncthreads();
        }
        // convergence check (swmax warp-uniform after butterfly)
        if (lane == 0) wred[warp] = swmax;
        __syncthreads();
        if (t == 0) {
            float m = wred[0];
            for (int i = 1; i < 8; ++i) m = fmaxf(m, wred[i]);
            conv_s = (m < convthr) ? 1 : 0;
        }
        __syncthreads();
        if (conv_s) break;
    }

    // exact column norms (double), lambda = ||u|| - sigma, scale g = f/||u||^2
    if (t < 64) {
        const float* uc = U + t * UPAD;
        double s = 0.0;
        #pragma unroll 8
        for (int r_ = 0; r_ < 64; ++r_) { double v = (double)uc[r_]; s += v * v; }
        double rho = sqrt(s);
        float lam = (float)(rho - (double)sigma);
        float f = logf(fmaxf(lam, 1e-4f));
        gsc[t] = (float)((double)f / s);
    }
    __syncthreads();

    // L[i][j] = sum_m gsc[m] * U[m][i] * U[m][j]; thread: row i0 x 16-col chunk
    const int i0 = t >> 2;
    const int j0 = (t & 3) << 4;
    float acc16[16];
    #pragma unroll
    for (int jj = 0; jj < 16; ++jj) acc16[jj] = 0.f;
    #pragma unroll 4
    for (int m = 0; m < 64; ++m) {
        float a = gsc[m] * U[m * UPAD + i0];
        const float* ur = U + m * UPAD + j0;
        #pragma unroll
        for (int jj = 0; jj < 16; ++jj) acc16[jj] += a * ur[jj];
    }
    float lsum = 0.f, lsq = 0.f;
    float* dst = g_lbuf + (size_t)b * 4096;
    #pragma unroll
    for (int jj = 0; jj < 16; ++jj) {
        float v = acc16[jj];
        dst[i0 * 64 + j0 + jj] = v;
        lsum += v; lsq += v * v;
    }
    #pragma unroll
    for (int off = 16; off; off >>= 1) {
        lsum += __shfl_down_sync(0xffffffffu, lsum, off);
        lsq  += __shfl_down_sync(0xffffffffu, lsq, off);
    }
    if (lane == 0) { wred[warp] = lsum; wred[8 + warp] = lsq; }
    __syncthreads();
    if (t == 0) {
        float s1 = 0.f, s2 = 0.f;
        for (int i = 0; i < 8; ++i) { s1 += wred[i]; s2 += wred[8 + i]; }
        g_eusum[b] = s1;
        g_eusq[b]  = s2;
    }
}

// ---------------- K2: block 1  (matnorm(eu) @ w2 -> relu -> @w3 + eu) ----------------
__global__ __launch_bounds__(128) void dense1_kernel(const float* __restrict__ w2, const float* __restrict__ b2,
                                                     const float* __restrict__ w3, const float* __restrict__ b3) {
    const int t = threadIdx.x;
    const int n = blockIdx.y;
    const int pos = blockIdx.x * 128 + t;
    __shared__ float sw2[1024], sw3[1024], sb2[32], sb3[32];
    __shared__ float meanS[22], isdS[22], em3S[10];
    __shared__ float acc1[32], acc2[32];
    for (int i = t; i < 1024; i += 128) { sw2[i] = w2[i]; sw3[i] = w3[i]; }
    if (t < 32) { sb2[t] = b2[t]; sb3[t] = b3[t]; acc1[t] = 0.f; acc2[t] = 0.f; }
    if (t < 22) {
        float mu = g_eusum[n * 22 + t] * (1.f / 4096.f);
        float var = fmaxf(g_eusq[n * 22 + t] * (1.f / 4096.f) - mu * mu, 0.f);
        meanS[t] = mu;
        isdS[t] = 1.f / fmaxf(sqrtf(var), 1e-3f);   // matnorm: clamp OUTSIDE sqrt
    }
    if (t < 10) em3S[t] = g_em3[t];
    __syncthreads();

    float eu[32];
    #pragma unroll
    for (int c = 0; c < 22; ++c) eu[c] = g_lbuf[((size_t)n * 22 + c) * 4096 + pos];
    #pragma unroll
    for (int c = 22; c < 32; ++c) eu[c] = em3S[c - 22];
    float mt[22];
    #pragma unroll
    for (int c = 0; c < 22; ++c) mt[c] = (eu[c] - meanS[c]) * isdS[c];
    // matnorm of the constant embedding channels is exactly 0 (std clamped), so skip c>=22
    float res[32];
    #pragma unroll
    for (int o = 0; o < 32; ++o) {
        float a = sb2[o];
        #pragma unroll
        for (int c = 0; c < 22; ++c) a += mt[c] * sw2[c * 32 + o];
        res[o] = fmaxf(a, 0.f);
    }
    #pragma unroll
    for (int o = 0; o < 32; ++o) {
        float a = sb3[o];
        #pragma unroll
        for (int c = 0; c < 32; ++c) a += res[c] * sw3[c * 32 + o];
        float h = eu[o] + a;
        g_h2[((size_t)n * 32 + o) * 4096 + pos] = h;
        float s1 = h, s2 = h * h;
        #pragma unroll
        for (int off = 16; off; off >>= 1) {
            s1 += __shfl_down_sync(0xffffffffu, s1, off);
            s2 += __shfl_down_sync(0xffffffffu, s2, off);
        }
        if ((t & 31) == 0) { atomicAdd(&acc1[o], s1); atomicAdd(&acc2[o], s2); }
    }
    __syncthreads();
    if (t < 32) {
        atomicAdd(&g_h2sum[n * 32 + t], acc1[t]);
        atomicAdd(&g_h2sq[n * 32 + t], acc2[t]);
    }
}

// ---------------- K3: block 2  (matnorm(h2) @ w4 -> relu -> @w5 + h2, mean) ----------------
__global__ __launch_bounds__(128) void dense2_kernel(const float* __restrict__ w4, const float* __restrict__ b4,
                                                     const float* __restrict__ w5, const float* __restrict__ b5) {
    const int t = threadIdx.x;
    const int n = blockIdx.y;
    const int pos = blockIdx.x * 128 + t;
    __shared__ float sw4[1024], sw5[1024], sb4[32], sb5[32];
    __shared__ float meanS[32], isdS[32];
    __shared__ float acc1[32];
    for (int i = t; i < 1024; i += 128) { sw4[i] = w4[i]; sw5[i] = w5[i]; }
    if (t < 32) {
        sb4[t] = b4[t]; sb5[t] = b5[t]; acc1[t] = 0.f;
        float mu = g_h2sum[n * 32 + t] * (1.f / 4096.f);
        float var = fmaxf(g_h2sq[n * 32 + t] * (1.f / 4096.f) - mu * mu, 0.f);
        meanS[t] = mu;
        isdS[t] = 1.f / fmaxf(sqrtf(var), 1e-3f);
    }
    __syncthreads();

    float hv[32];
    #pragma unroll
    for (int c = 0; c < 32; ++c) hv[c] = g_h2[((size_t)n * 32 + c) * 4096 + pos];
    float mt[32];
    #pragma unroll
    for (int c = 0; c < 32; ++c) mt[c] = (hv[c] - meanS[c]) * isdS[c];
    float res[32];
    #pragma unroll
    for (int o = 0; o < 32; ++o) {
        float a = sb4[o];
        #pragma unroll
        for (int c = 0; c < 32; ++c) a += mt[c] * sw4[c * 32 + o];
        res[o] = fmaxf(a, 0.f);
    }
    #pragma unroll
    for (int o = 0; o < 32; ++o) {
        float a = sb5[o];
        #pragma unroll
        for (int c = 0; c < 32; ++c) a += res[c] * sw5[c * 32 + o];
        float h = hv[o] + a;
        float s1 = h;
        #pragma unroll
        for (int off = 16; off; off >>= 1) s1 += __shfl_down_sync(0xffffffffu, s1, off);
        if ((t & 31) == 0) atomicAdd(&acc1[o], s1);
    }
    __syncthreads();
    if (t < 32) atomicAdd(&g_cov3[n * 32 + t], acc1[t]);
}

// ---------------- K4: head (cov3 @ w -> softmax) ----------------
__global__ void head_kernel(const float* __restrict__ w, float* __restrict__ out) {
    const int n = threadIdx.x;  // 256 threads
    float c[32];
    #pragma unroll
    for (int ch = 0; ch < 32; ++ch) c[ch] = g_cov3[n * 32 + ch] * (1.f / 4096.f);
    float lg[7];
    #pragma unroll
    for (int cls = 0; cls < 7; ++cls) {
        float a = 0.f;
        #pragma unroll
        for (int ch = 0; ch < 32; ++ch) a += c[ch] * w[ch * 7 + cls];
        lg[cls] = a;
    }
    float mx = lg[0];
    #pragma unroll
    for (int cls = 1; cls < 7; ++cls) mx = fmaxf(mx, lg[cls]);
    float sum = 0.f;
    #pragma unroll
    for (int cls = 0; cls < 7; ++cls) { lg[cls] = expf(lg[cls] - mx); sum += lg[cls]; }
    float inv = 1.f / sum;
    #pragma unroll
    for (int cls = 0; cls < 7; ++cls) out[n * 7 + cls] = lg[cls] * inv;
}

// ---------------- launch ----------------
extern "C" void kernel_launch(void* const* d_in, const int* in_sizes, int n_in,
                              void* d_out, int out_size) {
    const float* x   = (const float*)d_in[0];
    const void*  M   = d_in[1];
    const float* w   = (const float*)d_in[2];
    const float* w2  = (const float*)d_in[3];
    const float* b2  = (const float*)d_in[4];
    const float* w3  = (const float*)d_in[5];
    const float* b3  = (const float*)d_in[6];
    const float* w4  = (const float*)d_in[7];
    const float* b4  = (const float*)d_in[8];
    const float* w5  = (const float*)d_in[9];
    const float* b5  = (const float*)d_in[10];
    const float* we1 = (const float*)d_in[11];
    const float* be1 = (const float*)d_in[12];
    const float* we2 = (const float*)d_in[13];
    const float* be2 = (const float*)d_in[14];
    const float* we3 = (const float*)d_in[15];
    const float* be3 = (const float*)d_in[16];
    const float* lng = (const float*)d_in[17];
    const float* lnb = (const float*)d_in[18];

    init_kernel<<<1, 256>>>(M, we1, be1, we2, be2, we3, be3, lng, lnb);
    eig_kernel<<<256 * 22, 256>>>(x);
    dense1_kernel<<<dim3(32, 256), 128>>>(w2, b2, w3, b3);
    dense2_kernel<<<dim3(32, 256), 128>>>(w4, b4, w5, b5);
    head_kernel<<<1, 256>>>(w, (float*)d_out);
}

// round 10
// speedup vs baseline: 1.8981x; 1.5397x over previous
#include <cuda_runtime.h>
#include <cuda_bf16.h>
#include <math.h>

// ---------------- scratch (static device globals; no allocation) ----------------
__device__ float g_lbuf[256 * 22 * 4096];   // log-eig planes, layout [n][ch][pos]
__device__ float g_h2[256 * 32 * 4096];     // h2, layout [n][ch][pos]
__device__ float g_eusum[256 * 22];
__device__ float g_eusq[256 * 22];
__device__ float g_h2sum[256 * 32];
__device__ float g_h2sq[256 * 32];
__device__ float g_cov3[256 * 32];
__device__ float g_em3[10];

#define MAXSWEEPS 10
#define UPAD 68   // column stride (floats); 68*4B=272B, 16B-aligned for float4

// round-robin pairing: round r in [0,63), pair k in [0,32)
__device__ __forceinline__ void pairpq(int r, int k, int& p, int& q) {
    if (k == 0) { p = 63; q = r; }
    else {
        p = r + k; if (p >= 63) p -= 63;
        q = r - k; if (q < 0)  q += 63;
    }
}

// ---------------- K0: init accumulators + scalar-embedding MLP ----------------
__global__ void init_kernel(const void* __restrict__ Mraw,
                            const float* __restrict__ we1, const float* __restrict__ be1,
                            const float* __restrict__ we2, const float* __restrict__ be2,
                            const float* __restrict__ we3, const float* __restrict__ be3,
                            const float* __restrict__ ln_g, const float* __restrict__ ln_b) {
    const int t = threadIdx.x;  // 256 threads, 1 block
    for (int i = t; i < 256 * 32; i += 256) {
        g_h2sum[i] = 0.f; g_h2sq[i] = 0.f; g_cov3[i] = 0.f;
    }
    __shared__ float md[2];
    __shared__ float em[10], emln[10], em2[100];
    __shared__ float mu_s, isd_s;
    if (t == 0) {
        int mi = *(const int*)Mraw;
        float Mv = (mi > 0 && mi < 100000000) ? (float)mi : __int_as_float(mi);
        md[0] = Mv / 500.0f;
        md[1] = 64.0f / 100.0f;
    }
    __syncthreads();
    if (t < 10) em[t] = md[0] * we1[t] + md[1] * we1[10 + t] + be1[t];
    __syncthreads();
    if (t == 0) {
        float s = 0.f, s2 = 0.f;
        for (int j = 0; j < 10; ++j) { s += em[j]; s2 += em[j] * em[j]; }
        float mu = s * 0.1f;
        float var = fmaxf(s2 * 0.1f - mu * mu, 0.f);
        mu_s = mu;
        isd_s = rsqrtf(var + 1e-3f);   // keras LN: eps inside sqrt
    }
    __syncthreads();
    if (t < 10) emln[t] = (em[t] - mu_s) * isd_s * ln_g[t] + ln_b[t];
    __syncthreads();
    if (t < 100) {
        float a = be2[t];
        for (int j = 0; j < 10; ++j) a += emln[j] * we2[j * 100 + t];
        em2[t] = fmaxf(a, 0.f);
    }
    __syncthreads();
    if (t < 10) {
        float a = be3[t];
        for (int k = 0; k < 100; ++k) a += em2[k] * we3[k * 10 + t];
        g_em3[t] = em[t] + a;
    }
}

// ---------------- K1: shifted one-sided Jacobi, V-free, half-warp pairs ----------
// U = A + sigma*I (PD, sigma = ||A||_F), column-major (stride UPAD).
// Each HALF-WARP owns one pair: 16 lanes x float4 = 64-row column. One warp
// processes 2 pairs per instruction stream; 2 iterations cover its 4 pairs.
// Butterfly reduce is 4 levels (offsets 8,4,2,1; confined to each half).
// lambda_c = ||u_c|| - sigma; L = sum_c (f_c/||u_c||^2) u_c u_c^T.
__global__ __launch_bounds__(256, 5) void eig_kernel(const float* __restrict__ x) {
    __shared__ __align__(16) float U[64 * UPAD];
    __shared__ float nrm[64];
    __shared__ float gsc[64];
    __shared__ float wred[16];
    __shared__ float sig_s, sig2_s;
    __shared__ int conv_s;

    const int t = threadIdx.x;
    const int warp = t >> 5, lane = t & 31;
    const int b = blockIdx.x;      // n*22 + ch
    const float* src = x + (size_t)b * 4096;

    // load plane (coalesced) into U column-major
    #pragma unroll
    for (int it = 0; it < 16; ++it) {
        int id = t + 256 * it;
        int r_ = id >> 6, c_ = id & 63;
        U[c_ * UPAD + r_] = src[id];
    }
    __syncthreads();
    // symmetrize in smem + Frobenius norm^2
    float fn = 0.f;
    #pragma unroll
    for (int it = 0; it < 16; ++it) {
        int id = t + 256 * it;
        int i = id >> 6, j = id & 63;
        if (i < j) {
            float a = 0.5f * (U[i * UPAD + j] + U[j * UPAD + i]);
            U[i * UPAD + j] = a; U[j * UPAD + i] = a;
            fn += 2.f * a * a;
        } else if (i == j) {
            float d = U[i * UPAD + i];
            fn += d * d;
        }
    }
    #pragma unroll
    for (int off = 16; off; off >>= 1) fn += __shfl_xor_sync(0xffffffffu, fn, off);
    if (lane == 0) wred[warp] = fn;
    __syncthreads();
    if (t == 0) {
        float s = 0.f;
        for (int i = 0; i < 8; ++i) s += wred[i];
        sig2_s = s;
        sig_s = sqrtf(s);
        conv_s = 0;
    }
    __syncthreads();
    const float sigma = sig_s;
    if (t < 64) U[t * UPAD + t] += sigma;   // shift: U = A + sigma*I  (PD)
    __syncthreads();
    // initial column sq-norms (one-time)
    if (t < 64) {
        const float* uc = U + t * UPAD;
        float s = 0.f;
        #pragma unroll 8
        for (int r_ = 0; r_ < 64; ++r_) { float v = uc[r_]; s += v * v; }
        nrm[t] = s;
    }
    __syncthreads();

    const float skipthr = 1e-5f * sig2_s + 1e-30f;
    const float convthr = 1e-4f * sig2_s + 1e-30f;

    const int hl = lane & 15;            // lane within half-warp
    const int half = lane >> 4;          // 0 or 1

    for (int sweep = 0; sweep < MAXSWEEPS; ++sweep) {
        float swmax = 0.f;
        for (int r = 0; r < 63; ++r) {
            #pragma unroll
            for (int it2 = 0; it2 < 2; ++it2) {
                int k = (warp << 2) | (it2 << 1) | half;   // this half's pair
                int p, q; pairpq(r, k, p, q);
                float4* Up = (float4*)(U + p * UPAD);
                float4* Uq = (float4*)(U + q * UPAD);
                float4 up = Up[hl], uq = Uq[hl];
                float spq = up.x * uq.x + up.y * uq.y + up.z * uq.z + up.w * uq.w;
                #pragma unroll
                for (int off = 8; off; off >>= 1)
                    spq += __shfl_xor_sync(0xffffffffu, spq, off);
                swmax = fmaxf(swmax, fabsf(spq));
                if (fabsf(spq) > skipthr) {
                    float dpp = nrm[p], dqq = nrm[q];    // broadcast LDS per half
                    float tau = (dqq - dpp) / (2.f * spq);
                    float tt = copysignf(1.f, tau) / (fabsf(tau) + sqrtf(1.f + tau * tau));
                    float c = rsqrtf(1.f + tt * tt);
                    float s = tt * c;
                    float4 np, nq;
                    np.x = c * up.x - s * uq.x;  np.y = c * up.y - s * uq.y;
                    np.z = c * up.z - s * uq.z;  np.w = c * up.w - s * uq.w;
                    nq.x = s * up.x + c * uq.x;  nq.y = s * up.y + c * uq.y;
                    nq.z = s * up.z + c * uq.z;  nq.w = s * up.w + c * uq.w;
                    Up[hl] = np; Uq[hl] = nq;
                    if (hl == 0) {                       // lanes 0 and 16
                        float cc = c * c, ss = s * s, cs2 = 2.f * c * s * spq;
                        nrm[p] = cc * dpp + ss * dqq - cs2;
                        nrm[q] = ss * dpp + cc * dqq + cs2;
                    }
                }
            }
            __syncthreads();
        }
        // merge the two halves' swmax, then block-reduce
        swmax = fmaxf(swmax, __shfl_xor_sync(0xffffffffu, swmax, 16));
        if (lane == 0) wred[warp] = swmax;
        __syncthreads();
        if (t == 0) {
            float m = wred[0];
            for (int i = 1; i < 8; ++i) m = fmaxf(m, wred[i]);
            conv_s = (m < convthr) ? 1 : 0;
        }
        __syncthreads();
        if (conv_s) break;
    }

    // exact column norms (double), lambda = ||u|| - sigma, scale g = f/||u||^2
    if (t < 64) {
        const float* uc = U + t * UPAD;
        double s = 0.0;
        #pragma unroll 8
        for (int r_ = 0; r_ < 64; ++r_) { double v = (double)uc[r_]; s += v * v; }
        double rho = sqrt(s);
        float lam = (float)(rho - (double)sigma);
        float f = logf(fmaxf(lam, 1e-4f));
        gsc[t] = (float)((double)f / s);
    }
    __syncthreads();

    // L[i][j] = sum_m gsc[m] * U[m][i] * U[m][j]; thread: row i0 x 16-col chunk
    const int i0 = t >> 2;
    const int j0 = (t & 3) << 4;
    float acc16[16];
    #pragma unroll
    for (int jj = 0; jj < 16; ++jj) acc16[jj] = 0.f;
    #pragma unroll 4
    for (int m = 0; m < 64; ++m) {
        float a = gsc[m] * U[m * UPAD + i0];
        const float* ur = U + m * UPAD + j0;
        #pragma unroll
        for (int jj = 0; jj < 16; ++jj) acc16[jj] += a * ur[jj];
    }
    float lsum = 0.f, lsq = 0.f;
    float* dst = g_lbuf + (size_t)b * 4096;
    #pragma unroll
    for (int jj = 0; jj < 16; ++jj) {
        float v = acc16[jj];
        dst[i0 * 64 + j0 + jj] = v;
        lsum += v; lsq += v * v;
    }
    #pragma unroll
    for (int off = 16; off; off >>= 1) {
        lsum += __shfl_down_sync(0xffffffffu, lsum, off);
        lsq  += __shfl_down_sync(0xffffffffu, lsq, off);
    }
    if (lane == 0) { wred[warp] = lsum; wred[8 + warp] = lsq; }
    __syncthreads();
    if (t == 0) {
        float s1 = 0.f, s2 = 0.f;
        for (int i = 0; i < 8; ++i) { s1 += wred[i]; s2 += wred[8 + i]; }
        g_eusum[b] = s1;
        g_eusq[b]  = s2;
    }
}

// ---------------- K2: block 1  (matnorm(eu) @ w2 -> relu -> @w3 + eu) ----------------
__global__ __launch_bounds__(128) void dense1_kernel(const float* __restrict__ w2, const float* __restrict__ b2,
                                                     const float* __restrict__ w3, const float* __restrict__ b3) {
    const int t = threadIdx.x;
    const int n = blockIdx.y;
    const int pos = blockIdx.x * 128 + t;
    __shared__ float sw2[1024], sw3[1024], sb2[32], sb3[32];
    __shared__ float meanS[22], isdS[22], em3S[10];
    __shared__ float acc1[32], acc2[32];
    for (int i = t; i < 1024; i += 128) { sw2[i] = w2[i]; sw3[i] = w3[i]; }
    if (t < 32) { sb2[t] = b2[t]; sb3[t] = b3[t]; acc1[t] = 0.f; acc2[t] = 0.f; }
    if (t < 22) {
        float mu = g_eusum[n * 22 + t] * (1.f / 4096.f);
        float var = fmaxf(g_eusq[n * 22 + t] * (1.f / 4096.f) - mu * mu, 0.f);
        meanS[t] = mu;
        isdS[t] = 1.f / fmaxf(sqrtf(var), 1e-3f);   // matnorm: clamp OUTSIDE sqrt
    }
    if (t < 10) em3S[t] = g_em3[t];
    __syncthreads();

    float eu[32];
    #pragma unroll
    for (int c = 0; c < 22; ++c) eu[c] = g_lbuf[((size_t)n * 22 + c) * 4096 + pos];
    #pragma unroll
    for (int c = 22; c < 32; ++c) eu[c] = em3S[c - 22];
    float mt[22];
    #pragma unroll
    for (int c = 0; c < 22; ++c) mt[c] = (eu[c] - meanS[c]) * isdS[c];
    // matnorm of the constant embedding channels is exactly 0 (std clamped), so skip c>=22
    float res[32];
    #pragma unroll
    for (int o = 0; o < 32; ++o) {
        float a = sb2[o];
        #pragma unroll
        for (int c = 0; c < 22; ++c) a += mt[c] * sw2[c * 32 + o];
        res[o] = fmaxf(a, 0.f);
    }
    #pragma unroll
    for (int o = 0; o < 32; ++o) {
        float a = sb3[o];
        #pragma unroll
        for (int c = 0; c < 32; ++c) a += res[c] * sw3[c * 32 + o];
        float h = eu[o] + a;
        g_h2[((size_t)n * 32 + o) * 4096 + pos] = h;
        float s1 = h, s2 = h * h;
        #pragma unroll
        for (int off = 16; off; off >>= 1) {
            s1 += __shfl_down_sync(0xffffffffu, s1, off);
            s2 += __shfl_down_sync(0xffffffffu, s2, off);
        }
        if ((t & 31) == 0) { atomicAdd(&acc1[o], s1); atomicAdd(&acc2[o], s2); }
    }
    __syncthreads();
    if (t < 32) {
        atomicAdd(&g_h2sum[n * 32 + t], acc1[t]);
        atomicAdd(&g_h2sq[n * 32 + t], acc2[t]);
    }
}

// ---------------- K3: block 2  (matnorm(h2) @ w4 -> relu -> @w5 + h2, mean) ----------------
__global__ __launch_bounds__(128) void dense2_kernel(const float* __restrict__ w4, const float* __restrict__ b4,
                                                     const float* __restrict__ w5, const float* __restrict__ b5) {
    const int t = threadIdx.x;
    const int n = blockIdx.y;
    const int pos = blockIdx.x * 128 + t;
    __shared__ float sw4[1024], sw5[1024], sb4[32], sb5[32];
    __shared__ float meanS[32], isdS[32];
    __shared__ float acc1[32];
    for (int i = t; i < 1024; i += 128) { sw4[i] = w4[i]; sw5[i] = w5[i]; }
    if (t < 32) {
        sb4[t] = b4[t]; sb5[t] = b5[t]; acc1[t] = 0.f;
        float mu = g_h2sum[n * 32 + t] * (1.f / 4096.f);
        float var = fmaxf(g_h2sq[n * 32 + t] * (1.f / 4096.f) - mu * mu, 0.f);
        meanS[t] = mu;
        isdS[t] = 1.f / fmaxf(sqrtf(var), 1e-3f);
    }
    __syncthreads();

    float hv[32];
    #pragma unroll
    for (int c = 0; c < 32; ++c) hv[c] = g_h2[((size_t)n * 32 + c) * 4096 + pos];
    float mt[32];
    #pragma unroll
    for (int c = 0; c < 32; ++c) mt[c] = (hv[c] - meanS[c]) * isdS[c];
    float res[32];
    #pragma unroll
    for (int o = 0; o < 32; ++o) {
        float a = sb4[o];
        #pragma unroll
        for (int c = 0; c < 32; ++c) a += mt[c] * sw4[c * 32 + o];
        res[o] = fmaxf(a, 0.f);
    }
    #pragma unroll
    for (int o = 0; o < 32; ++o) {
        float a = sb5[o];
        #pragma unroll
        for (int c = 0; c < 32; ++c) a += res[c] * sw5[c * 32 + o];
        float h = hv[o] + a;
        float s1 = h;
        #pragma unroll
        for (int off = 16; off; off >>= 1) s1 += __shfl_down_sync(0xffffffffu, s1, off);
        if ((t & 31) == 0) atomicAdd(&acc1[o], s1);
    }
    __syncthreads();
    if (t < 32) atomicAdd(&g_cov3[n * 32 + t], acc1[t]);
}

// ---------------- K4: head (cov3 @ w -> softmax) ----------------
__global__ void head_kernel(const float* __restrict__ w, float* __restrict__ out) {
    const int n = threadIdx.x;  // 256 threads
    float c[32];
    #pragma unroll
    for (int ch = 0; ch < 32; ++ch) c[ch] = g_cov3[n * 32 + ch] * (1.f / 4096.f);
    float lg[7];
    #pragma unroll
    for (int cls = 0; cls < 7; ++cls) {
        float a = 0.f;
        #pragma unroll
        for (int ch = 0; ch < 32; ++ch) a += c[ch] * w[ch * 7 + cls];
        lg[cls] = a;
    }
    float mx = lg[0];
    #pragma unroll
    for (int cls = 1; cls < 7; ++cls) mx = fmaxf(mx, lg[cls]);
    float sum = 0.f;
    #pragma unroll
    for (int cls = 0; cls < 7; ++cls) { lg[cls] = expf(lg[cls] - mx); sum += lg[cls]; }
    float inv = 1.f / sum;
    #pragma unroll
    for (int cls = 0; cls < 7; ++cls) out[n * 7 + cls] = lg[cls] * inv;
}

// ---------------- launch ----------------
extern "C" void kernel_launch(void* const* d_in, const int* in_sizes, int n_in,
                              void* d_out, int out_size) {
    const float* x   = (const float*)d_in[0];
    const void*  M   = d_in[1];
    const float* w   = (const float*)d_in[2];
    const float* w2  = (const float*)d_in[3];
    const float* b2  = (const float*)d_in[4];
    const float* w3  = (const float*)d_in[5];
    const float* b3  = (const float*)d_in[6];
    const float* w4  = (const float*)d_in[7];
    const float* b4  = (const float*)d_in[8];
    const float* w5  = (const float*)d_in[9];
    const float* b5  = (const float*)d_in[10];
    const float* we1 = (const float*)d_in[11];
    const float* be1 = (const float*)d_in[12];
    const float* we2 = (const float*)d_in[13];
    const float* be2 = (const float*)d_in[14];
    const float* we3 = (const float*)d_in[15];
    const float* be3 = (const float*)d_in[16];
    const float* lng = (const float*)d_in[17];
    const float* lnb = (const float*)d_in[18];

    init_kernel<<<1, 256>>>(M, we1, be1, we2, be2, we3, be3, lng, lnb);
    eig_kernel<<<256 * 22, 256>>>(x);
    dense1_kernel<<<dim3(32, 256), 128>>>(w2, b2, w3, b3);
    dense2_kernel<<<dim3(32, 256), 128>>>(w4, b4, w5, b5);
    head_kernel<<<1, 256>>>(w, (float*)d_out);
}

// round 11
// speedup vs baseline: 2.4550x; 1.2934x over previous
#include <cuda_runtime.h>
#include <cuda_bf16.h>
#include <math.h>

// ---------------- scratch (static device globals; no allocation) ----------------
__device__ float g_lbuf[256 * 22 * 4096];   // log-eig planes, layout [n][ch][pos]
__device__ float g_h2[256 * 32 * 4096];     // h2, layout [n][ch][pos]
__device__ float g_eusum[256 * 22];
__device__ float g_eusq[256 * 22];
__device__ float g_h2sum[256 * 32];
__device__ float g_h2sq[256 * 32];
__device__ float g_cov3[256 * 32];
__device__ float g_em3[10];

#define MAXSWEEPS 10
#define UPAD 68   // column stride (floats); 68*4B=272B, 16B-aligned for float4

// round-robin pairing: round r in [0,63), pair k in [0,32)
__device__ __forceinline__ void pairpq(int r, int k, int& p, int& q) {
    if (k == 0) { p = 63; q = r; }
    else {
        p = r + k; if (p >= 63) p -= 63;
        q = r - k; if (q < 0)  q += 63;
    }
}

// ---------------- K0: init accumulators + scalar-embedding MLP ----------------
__global__ void init_kernel(const void* __restrict__ Mraw,
                            const float* __restrict__ we1, const float* __restrict__ be1,
                            const float* __restrict__ we2, const float* __restrict__ be2,
                            const float* __restrict__ we3, const float* __restrict__ be3,
                            const float* __restrict__ ln_g, const float* __restrict__ ln_b) {
    const int t = threadIdx.x;  // 256 threads, 1 block
    for (int i = t; i < 256 * 32; i += 256) {
        g_h2sum[i] = 0.f; g_h2sq[i] = 0.f; g_cov3[i] = 0.f;
    }
    __shared__ float md[2];
    __shared__ float em[10], emln[10], em2[100];
    __shared__ float mu_s, isd_s;
    if (t == 0) {
        int mi = *(const int*)Mraw;
        float Mv = (mi > 0 && mi < 100000000) ? (float)mi : __int_as_float(mi);
        md[0] = Mv / 500.0f;
        md[1] = 64.0f / 100.0f;
    }
    __syncthreads();
    if (t < 10) em[t] = md[0] * we1[t] + md[1] * we1[10 + t] + be1[t];
    __syncthreads();
    if (t == 0) {
        float s = 0.f, s2 = 0.f;
        for (int j = 0; j < 10; ++j) { s += em[j]; s2 += em[j] * em[j]; }
        float mu = s * 0.1f;
        float var = fmaxf(s2 * 0.1f - mu * mu, 0.f);
        mu_s = mu;
        isd_s = rsqrtf(var + 1e-3f);   // keras LN: eps inside sqrt
    }
    __syncthreads();
    if (t < 10) emln[t] = (em[t] - mu_s) * isd_s * ln_g[t] + ln_b[t];
    __syncthreads();
    if (t < 100) {
        float a = be2[t];
        for (int j = 0; j < 10; ++j) a += emln[j] * we2[j * 100 + t];
        em2[t] = fmaxf(a, 0.f);
    }
    __syncthreads();
    if (t < 10) {
        float a = be3[t];
        for (int k = 0; k < 100; ++k) a += em2[k] * we3[k * 10 + t];
        g_em3[t] = em[t] + a;
    }
}

// ---------------- K1: shifted one-sided Jacobi, V-free, quarter-warp pairs --------
// U = A + sigma*I (PD, sigma = ||A||_F), column-major (stride UPAD).
// Each 8-lane QUARTER-warp owns one pair; a lane holds 2xfloat4 per column
// (rows ql*4..ql*4+3 and 32+ql*4..). One warp retires its 4 pairs in a single
// instruction stream; butterfly reduce is 3 levels (offsets 4,2,1).
// lambda_c = ||u_c|| - sigma; L = sum_c (f_c/||u_c||^2) u_c u_c^T.
__global__ __launch_bounds__(256, 5) void eig_kernel(const float* __restrict__ x) {
    __shared__ __align__(16) float U[64 * UPAD];
    __shared__ float nrm[64];
    __shared__ float gsc[64];
    __shared__ float wred[16];
    __shared__ float sig_s, sig2_s;
    __shared__ int conv_s;

    const int t = threadIdx.x;
    const int warp = t >> 5, lane = t & 31;
    const int b = blockIdx.x;      // n*22 + ch
    const float* src = x + (size_t)b * 4096;

    // load plane (coalesced) into U column-major
    #pragma unroll
    for (int it = 0; it < 16; ++it) {
        int id = t + 256 * it;
        int r_ = id >> 6, c_ = id & 63;
        U[c_ * UPAD + r_] = src[id];
    }
    __syncthreads();
    // symmetrize in smem + Frobenius norm^2
    float fn = 0.f;
    #pragma unroll
    for (int it = 0; it < 16; ++it) {
        int id = t + 256 * it;
        int i = id >> 6, j = id & 63;
        if (i < j) {
            float a = 0.5f * (U[i * UPAD + j] + U[j * UPAD + i]);
            U[i * UPAD + j] = a; U[j * UPAD + i] = a;
            fn += 2.f * a * a;
        } else if (i == j) {
            float d = U[i * UPAD + i];
            fn += d * d;
        }
    }
    #pragma unroll
    for (int off = 16; off; off >>= 1) fn += __shfl_xor_sync(0xffffffffu, fn, off);
    if (lane == 0) wred[warp] = fn;
    __syncthreads();
    if (t == 0) {
        float s = 0.f;
        for (int i = 0; i < 8; ++i) s += wred[i];
        sig2_s = s;
        sig_s = sqrtf(s);
        conv_s = 0;
    }
    __syncthreads();
    const float sigma = sig_s;
    if (t < 64) U[t * UPAD + t] += sigma;   // shift: U = A + sigma*I  (PD)
    __syncthreads();
    // initial column sq-norms (one-time)
    if (t < 64) {
        const float* uc = U + t * UPAD;
        float s = 0.f;
        #pragma unroll 8
        for (int r_ = 0; r_ < 64; ++r_) { float v = uc[r_]; s += v * v; }
        nrm[t] = s;
    }
    __syncthreads();

    const float skipthr = 1e-5f * sig2_s + 1e-30f;
    const float convthr = 1e-4f * sig2_s + 1e-30f;

    const int ql = lane & 7;             // lane within quarter
    const int quarter = lane >> 3;       // 0..3
    const int kpair = (warp << 2) | quarter;   // this quarter's pair index

    for (int sweep = 0; sweep < MAXSWEEPS; ++sweep) {
        float swmax = 0.f;
        for (int r = 0; r < 63; ++r) {
            int p, q; pairpq(r, kpair, p, q);
            float4* Up4 = (float4*)(U + p * UPAD);
            float4* Uq4 = (float4*)(U + q * UPAD);
            float4 a0 = Up4[ql], a1 = Up4[ql + 8];
            float4 b0 = Uq4[ql], b1 = Uq4[ql + 8];
            float spq = a0.x * b0.x + a0.y * b0.y + a0.z * b0.z + a0.w * b0.w
                      + a1.x * b1.x + a1.y * b1.y + a1.z * b1.z + a1.w * b1.w;
            #pragma unroll
            for (int off = 4; off; off >>= 1)
                spq += __shfl_xor_sync(0xffffffffu, spq, off);
            swmax = fmaxf(swmax, fabsf(spq));
            if (fabsf(spq) > skipthr) {
                float dpp = nrm[p], dqq = nrm[q];    // broadcast LDS per quarter
                float tau = (dqq - dpp) / (2.f * spq);
                float tt = copysignf(1.f, tau) / (fabsf(tau) + sqrtf(1.f + tau * tau));
                float c = rsqrtf(1.f + tt * tt);
                float s = tt * c;
                float4 n0, n1, m0, m1;
                n0.x = c * a0.x - s * b0.x;  n0.y = c * a0.y - s * b0.y;
                n0.z = c * a0.z - s * b0.z;  n0.w = c * a0.w - s * b0.w;
                n1.x = c * a1.x - s * b1.x;  n1.y = c * a1.y - s * b1.y;
                n1.z = c * a1.z - s * b1.z;  n1.w = c * a1.w - s * b1.w;
                m0.x = s * a0.x + c * b0.x;  m0.y = s * a0.y + c * b0.y;
                m0.z = s * a0.z + c * b0.z;  m0.w = s * a0.w + c * b0.w;
                m1.x = s * a1.x + c * b1.x;  m1.y = s * a1.y + c * b1.y;
                m1.z = s * a1.z + c * b1.z;  m1.w = s * a1.w + c * b1.w;
                Up4[ql] = n0; Up4[ql + 8] = n1;
                Uq4[ql] = m0; Uq4[ql + 8] = m1;
                if (ql == 0) {                       // lanes 0,8,16,24
                    float cc = c * c, ss = s * s, cs2 = 2.f * c * s * spq;
                    nrm[p] = cc * dpp + ss * dqq - cs2;
                    nrm[q] = ss * dpp + cc * dqq + cs2;
                }
            }
            __syncthreads();
        }
        // merge quarters' swmax, then block-reduce
        swmax = fmaxf(swmax, __shfl_xor_sync(0xffffffffu, swmax, 8));
        swmax = fmaxf(swmax, __shfl_xor_sync(0xffffffffu, swmax, 16));
        if (lane == 0) wred[warp] = swmax;
        __syncthreads();
        if (t == 0) {
            float m = wred[0];
            for (int i = 1; i < 8; ++i) m = fmaxf(m, wred[i]);
            conv_s = (m < convthr) ? 1 : 0;
        }
        __syncthreads();
        if (conv_s) break;
    }

    // exact column norms (double), lambda = ||u|| - sigma, scale g = f/||u||^2
    if (t < 64) {
        const float* uc = U + t * UPAD;
        double s = 0.0;
        #pragma unroll 8
        for (int r_ = 0; r_ < 64; ++r_) { double v = (double)uc[r_]; s += v * v; }
        double rho = sqrt(s);
        float lam = (float)(rho - (double)sigma);
        float f = logf(fmaxf(lam, 1e-4f));
        gsc[t] = (float)((double)f / s);
    }
    __syncthreads();

    // L[i][j] = sum_m gsc[m] * U[m][i] * U[m][j]; thread: row i0 x 16-col chunk
    const int i0 = t >> 2;
    const int j0 = (t & 3) << 4;
    float acc16[16];
    #pragma unroll
    for (int jj = 0; jj < 16; ++jj) acc16[jj] = 0.f;
    #pragma unroll 4
    for (int m = 0; m < 64; ++m) {
        float a = gsc[m] * U[m * UPAD + i0];
        const float* ur = U + m * UPAD + j0;
        #pragma unroll
        for (int jj = 0; jj < 16; ++jj) acc16[jj] += a * ur[jj];
    }
    float lsum = 0.f, lsq = 0.f;
    float* dst = g_lbuf + (size_t)b * 4096;
    #pragma unroll
    for (int jj = 0; jj < 16; ++jj) {
        float v = acc16[jj];
        dst[i0 * 64 + j0 + jj] = v;
        lsum += v; lsq += v * v;
    }
    #pragma unroll
    for (int off = 16; off; off >>= 1) {
        lsum += __shfl_down_sync(0xffffffffu, lsum, off);
        lsq  += __shfl_down_sync(0xffffffffu, lsq, off);
    }
    if (lane == 0) { wred[warp] = lsum; wred[8 + warp] = lsq; }
    __syncthreads();
    if (t == 0) {
        float s1 = 0.f, s2 = 0.f;
        for (int i = 0; i < 8; ++i) { s1 += wred[i]; s2 += wred[8 + i]; }
        g_eusum[b] = s1;
        g_eusq[b]  = s2;
    }
}

// ---------------- K2: block 1  (matnorm(eu) @ w2 -> relu -> @w3 + eu) ----------------
__global__ __launch_bounds__(128) void dense1_kernel(const float* __restrict__ w2, const float* __restrict__ b2,
                                                     const float* __restrict__ w3, const float* __restrict__ b3) {
    const int t = threadIdx.x;
    const int n = blockIdx.y;
    const int pos = blockIdx.x * 128 + t;
    __shared__ float sw2[1024], sw3[1024], sb2[32], sb3[32];
    __shared__ float meanS[22], isdS[22], em3S[10];
    __shared__ float acc1[32], acc2[32];
    for (int i = t; i < 1024; i += 128) { sw2[i] = w2[i]; sw3[i] = w3[i]; }
    if (t < 32) { sb2[t] = b2[t]; sb3[t] = b3[t]; acc1[t] = 0.f; acc2[t] = 0.f; }
    if (t < 22) {
        float mu = g_eusum[n * 22 + t] * (1.f / 4096.f);
        float var = fmaxf(g_eusq[n * 22 + t] * (1.f / 4096.f) - mu * mu, 0.f);
        meanS[t] = mu;
        isdS[t] = 1.f / fmaxf(sqrtf(var), 1e-3f);   // matnorm: clamp OUTSIDE sqrt
    }
    if (t < 10) em3S[t] = g_em3[t];
    __syncthreads();

    float eu[32];
    #pragma unroll
    for (int c = 0; c < 22; ++c) eu[c] = g_lbuf[((size_t)n * 22 + c) * 4096 + pos];
    #pragma unroll
    for (int c = 22; c < 32; ++c) eu[c] = em3S[c - 22];
    float mt[22];
    #pragma unroll
    for (int c = 0; c < 22; ++c) mt[c] = (eu[c] - meanS[c]) * isdS[c];
    // matnorm of the constant embedding channels is exactly 0 (std clamped), so skip c>=22
    float res[32];
    #pragma unroll
    for (int o = 0; o < 32; ++o) {
        float a = sb2[o];
        #pragma unroll
        for (int c = 0; c < 22; ++c) a += mt[c] * sw2[c * 32 + o];
        res[o] = fmaxf(a, 0.f);
    }
    #pragma unroll
    for (int o = 0; o < 32; ++o) {
        float a = sb3[o];
        #pragma unroll
        for (int c = 0; c < 32; ++c) a += res[c] * sw3[c * 32 + o];
        float h = eu[o] + a;
        g_h2[((size_t)n * 32 + o) * 4096 + pos] = h;
        float s1 = h, s2 = h * h;
        #pragma unroll
        for (int off = 16; off; off >>= 1) {
            s1 += __shfl_down_sync(0xffffffffu, s1, off);
            s2 += __shfl_down_sync(0xffffffffu, s2, off);
        }
        if ((t & 31) == 0) { atomicAdd(&acc1[o], s1); atomicAdd(&acc2[o], s2); }
    }
    __syncthreads();
    if (t < 32) {
        atomicAdd(&g_h2sum[n * 32 + t], acc1[t]);
        atomicAdd(&g_h2sq[n * 32 + t], acc2[t]);
    }
}

// ---------------- K3: block 2  (matnorm(h2) @ w4 -> relu -> @w5 + h2, mean) ----------------
__global__ __launch_bounds__(128) void dense2_kernel(const float* __restrict__ w4, const float* __restrict__ b4,
                                                     const float* __restrict__ w5, const float* __restrict__ b5) {
    const int t = threadIdx.x;
    const int n = blockIdx.y;
    const int pos = blockIdx.x * 128 + t;
    __shared__ float sw4[1024], sw5[1024], sb4[32], sb5[32];
    __shared__ float meanS[32], isdS[32];
    __shared__ float acc1[32];
    for (int i = t; i < 1024; i += 128) { sw4[i] = w4[i]; sw5[i] = w5[i]; }
    if (t < 32) {
        sb4[t] = b4[t]; sb5[t] = b5[t]; acc1[t] = 0.f;
        float mu = g_h2sum[n * 32 + t] * (1.f / 4096.f);
        float var = fmaxf(g_h2sq[n * 32 + t] * (1.f / 4096.f) - mu * mu, 0.f);
        meanS[t] = mu;
        isdS[t] = 1.f / fmaxf(sqrtf(var), 1e-3f);
    }
    __syncthreads();

    float hv[32];
    #pragma unroll
    for (int c = 0; c < 32; ++c) hv[c] = g_h2[((size_t)n * 32 + c) * 4096 + pos];
    float mt[32];
    #pragma unroll
    for (int c = 0; c < 32; ++c) mt[c] = (hv[c] - meanS[c]) * isdS[c];
    float res[32];
    #pragma unroll
    for (int o = 0; o < 32; ++o) {
        float a = sb4[o];
        #pragma unroll
        for (int c = 0; c < 32; ++c) a += mt[c] * sw4[c * 32 + o];
        res[o] = fmaxf(a, 0.f);
    }
    #pragma unroll
    for (int o = 0; o < 32; ++o) {
        float a = sb5[o];
        #pragma unroll
        for (int c = 0; c < 32; ++c) a += res[c] * sw5[c * 32 + o];
        float h = hv[o] + a;
        float s1 = h;
        #pragma unroll
        for (int off = 16; off; off >>= 1) s1 += __shfl_down_sync(0xffffffffu, s1, off);
        if ((t & 31) == 0) atomicAdd(&acc1[o], s1);
    }
    __syncthreads();
    if (t < 32) atomicAdd(&g_cov3[n * 32 + t], acc1[t]);
}

// ---------------- K4: head (cov3 @ w -> softmax) ----------------
__global__ void head_kernel(const float* __restrict__ w, float* __restrict__ out) {
    const int n = threadIdx.x;  // 256 threads
    float c[32];
    #pragma unroll
    for (int ch = 0; ch < 32; ++ch) c[ch] = g_cov3[n * 32 + ch] * (1.f / 4096.f);
    float lg[7];
    #pragma unroll
    for (int cls = 0; cls < 7; ++cls) {
        float a = 0.f;
        #pragma unroll
        for (int ch = 0; ch < 32; ++ch) a += c[ch] * w[ch * 7 + cls];
        lg[cls] = a;
    }
    float mx = lg[0];
    #pragma unroll
    for (int cls = 1; cls < 7; ++cls) mx = fmaxf(mx, lg[cls]);
    float sum = 0.f;
    #pragma unroll
    for (int cls = 0; cls < 7; ++cls) { lg[cls] = expf(lg[cls] - mx); sum += lg[cls]; }
    float inv = 1.f / sum;
    #pragma unroll
    for (int cls = 0; cls < 7; ++cls) out[n * 7 + cls] = lg[cls] * inv;
}

// ---------------- launch ----------------
extern "C" void kernel_launch(void* const* d_in, const int* in_sizes, int n_in,
                              void* d_out, int out_size) {
    const float* x   = (const float*)d_in[0];
    const void*  M   = d_in[1];
    const float* w   = (const float*)d_in[2];
    const float* w2  = (const float*)d_in[3];
    const float* b2  = (const float*)d_in[4];
    const float* w3  = (const float*)d_in[5];
    const float* b3  = (const float*)d_in[6];
    const float* w4  = (const float*)d_in[7];
    const float* b4  = (const float*)d_in[8];
    const float* w5  = (const float*)d_in[9];
    const float* b5  = (const float*)d_in[10];
    const float* we1 = (const float*)d_in[11];
    const float* be1 = (const float*)d_in[12];
    const float* we2 = (const float*)d_in[13];
    const float* be2 = (const float*)d_in[14];
    const float* we3 = (const float*)d_in[15];
    const float* be3 = (const float*)d_in[16];
    const float* lng = (const float*)d_in[17];
    const float* lnb = (const float*)d_in[18];

    init_kernel<<<1, 256>>>(M, we1, be1, we2, be2, we3, be3, lng, lnb);
    eig_kernel<<<256 * 22, 256>>>(x);
    dense1_kernel<<<dim3(32, 256), 128>>>(w2, b2, w3, b3);
    dense2_kernel<<<dim3(32, 256), 128>>>(w4, b4, w5, b5);
    head_kernel<<<1, 256>>>(w, (float*)d_out);
}

// round 12
// speedup vs baseline: 2.4933x; 1.0156x over previous
#include <cuda_runtime.h>
#include <cuda_bf16.h>
#include <math.h>

// ---------------- scratch (static device globals; no allocation) ----------------
__device__ float g_lbuf[256 * 22 * 4096];   // log-eig planes, layout [n][ch][pos]
__device__ float g_h2[256 * 32 * 4096];     // h2, layout [n][ch][pos]
__device__ float g_eusum[256 * 22];
__device__ float g_eusq[256 * 22];
__device__ float g_h2sum[256 * 32];
__device__ float g_h2sq[256 * 32];
__device__ float g_cov3[256 * 32];
__device__ float g_em3[10];

#define MAXSWEEPS 10
#define UPAD 68   // column stride (floats); 68*4B=272B, 16B-aligned

typedef unsigned long long ull;

// ---- packed f32x2 helpers (sm_103a; ptxas only emits FFMA2 via PTX) ----
__device__ __forceinline__ ull f2mul(ull a, ull b) {
    ull d; asm("mul.rn.f32x2 %0, %1, %2;" : "=l"(d) : "l"(a), "l"(b)); return d;
}
__device__ __forceinline__ ull f2fma(ull a, ull b, ull c) {
    ull d; asm("fma.rn.f32x2 %0, %1, %2, %3;" : "=l"(d) : "l"(a), "l"(b), "l"(c)); return d;
}
__device__ __forceinline__ ull f2pack(float lo, float hi) {
    ull d; asm("mov.b64 %0, {%1, %2};" : "=l"(d) : "f"(lo), "f"(hi)); return d;
}
__device__ __forceinline__ float2 f2unpack(ull v) {
    float lo, hi; asm("mov.b64 {%0, %1}, %2;" : "=f"(lo), "=f"(hi) : "l"(v));
    return make_float2(lo, hi);
}

// round-robin pairing: round r in [0,63), pair k in [0,32)
__device__ __forceinline__ void pairpq(int r, int k, int& p, int& q) {
    if (k == 0) { p = 63; q = r; }
    else {
        p = r + k; if (p >= 63) p -= 63;
        q = r - k; if (q < 0)  q += 63;
    }
}

// ---------------- K0: init accumulators + scalar-embedding MLP ----------------
__global__ void init_kernel(const void* __restrict__ Mraw,
                            const float* __restrict__ we1, const float* __restrict__ be1,
                            const float* __restrict__ we2, const float* __restrict__ be2,
                            const float* __restrict__ we3, const float* __restrict__ be3,
                            const float* __restrict__ ln_g, const float* __restrict__ ln_b) {
    const int t = threadIdx.x;  // 256 threads, 1 block
    for (int i = t; i < 256 * 32; i += 256) {
        g_h2sum[i] = 0.f; g_h2sq[i] = 0.f; g_cov3[i] = 0.f;
    }
    __shared__ float md[2];
    __shared__ float em[10], emln[10], em2[100];
    __shared__ float mu_s, isd_s;
    if (t == 0) {
        int mi = *(const int*)Mraw;
        float Mv = (mi > 0 && mi < 100000000) ? (float)mi : __int_as_float(mi);
        md[0] = Mv / 500.0f;
        md[1] = 64.0f / 100.0f;
    }
    __syncthreads();
    if (t < 10) em[t] = md[0] * we1[t] + md[1] * we1[10 + t] + be1[t];
    __syncthreads();
    if (t == 0) {
        float s = 0.f, s2 = 0.f;
        for (int j = 0; j < 10; ++j) { s += em[j]; s2 += em[j] * em[j]; }
        float mu = s * 0.1f;
        float var = fmaxf(s2 * 0.1f - mu * mu, 0.f);
        mu_s = mu;
        isd_s = rsqrtf(var + 1e-3f);   // keras LN: eps inside sqrt
    }
    __syncthreads();
    if (t < 10) emln[t] = (em[t] - mu_s) * isd_s * ln_g[t] + ln_b[t];
    __syncthreads();
    if (t < 100) {
        float a = be2[t];
        for (int j = 0; j < 10; ++j) a += emln[j] * we2[j * 100 + t];
        em2[t] = fmaxf(a, 0.f);
    }
    __syncthreads();
    if (t < 10) {
        float a = be3[t];
        for (int k = 0; k < 100; ++k) a += em2[k] * we3[k * 10 + t];
        g_em3[t] = em[t] + a;
    }
}

// ---------------- K1: shifted one-sided Jacobi, V-free, quarter-warp pairs --------
// U = A + sigma*I (PD, sigma = ||A||_F), column-major (stride UPAD).
// Each 8-lane quarter-warp owns one pair; lane holds 2x(f32x2 x2) per column.
// Rotation + dot use packed f32x2 FMA (FFMA pipe pressure ~halved).
// lambda_c = ||u_c|| - sigma; L = sum_c (f_c/||u_c||^2) u_c u_c^T.
__global__ __launch_bounds__(256, 5) void eig_kernel(const float* __restrict__ x) {
    __shared__ __align__(16) float U[64 * UPAD];
    __shared__ float nrm[64];
    __shared__ float gsc[64];
    __shared__ float wred[16];
    __shared__ float sig_s, sig2_s;
    __shared__ int conv_s;

    const int t = threadIdx.x;
    const int warp = t >> 5, lane = t & 31;
    const int b = blockIdx.x;      // n*22 + ch
    const float* src = x + (size_t)b * 4096;

    // load plane (coalesced) into U column-major
    #pragma unroll
    for (int it = 0; it < 16; ++it) {
        int id = t + 256 * it;
        int r_ = id >> 6, c_ = id & 63;
        U[c_ * UPAD + r_] = src[id];
    }
    __syncthreads();
    // symmetrize in smem + Frobenius norm^2
    float fn = 0.f;
    #pragma unroll
    for (int it = 0; it < 16; ++it) {
        int id = t + 256 * it;
        int i = id >> 6, j = id & 63;
        if (i < j) {
            float a = 0.5f * (U[i * UPAD + j] + U[j * UPAD + i]);
            U[i * UPAD + j] = a; U[j * UPAD + i] = a;
            fn += 2.f * a * a;
        } else if (i == j) {
            float d = U[i * UPAD + i];
            fn += d * d;
        }
    }
    #pragma unroll
    for (int off = 16; off; off >>= 1) fn += __shfl_xor_sync(0xffffffffu, fn, off);
    if (lane == 0) wred[warp] = fn;
    __syncthreads();
    if (t == 0) {
        float s = 0.f;
        for (int i = 0; i < 8; ++i) s += wred[i];
        sig2_s = s;
        sig_s = sqrtf(s);
        conv_s = 0;
    }
    __syncthreads();
    const float sigma = sig_s;
    if (t < 64) U[t * UPAD + t] += sigma;   // shift: U = A + sigma*I  (PD)
    __syncthreads();
    // initial column sq-norms (one-time)
    if (t < 64) {
        const float* uc = U + t * UPAD;
        float s = 0.f;
        #pragma unroll 8
        for (int r_ = 0; r_ < 64; ++r_) { float v = uc[r_]; s += v * v; }
        nrm[t] = s;
    }
    __syncthreads();

    const float skipthr = 4e-5f * sig2_s + 1e-30f;
    const float convthr = 4e-4f * sig2_s + 1e-30f;

    const int ql = lane & 7;             // lane within quarter
    const int quarter = lane >> 3;       // 0..3
    const int kpair = (warp << 2) | quarter;   // this quarter's pair index

    for (int sweep = 0; sweep < MAXSWEEPS; ++sweep) {
        float swmax = 0.f;
        for (int r = 0; r < 63; ++r) {
            int p, q; pairpq(r, kpair, p, q);
            ulonglong2* Up = (ulonglong2*)(U + p * UPAD);
            ulonglong2* Uq = (ulonglong2*)(U + q * UPAD);
            ulonglong2 A0 = Up[ql], A1 = Up[ql + 8];
            ulonglong2 B0 = Uq[ql], B1 = Uq[ql + 8];
            // packed dot: 4 fma.f32x2 + unpack-add
            ull acc = f2mul(A0.x, B0.x);
            acc = f2fma(A0.y, B0.y, acc);
            acc = f2fma(A1.x, B1.x, acc);
            acc = f2fma(A1.y, B1.y, acc);
            float2 ac = f2unpack(acc);
            float spq = ac.x + ac.y;
            #pragma unroll
            for (int off = 4; off; off >>= 1)
                spq += __shfl_xor_sync(0xffffffffu, spq, off);
            swmax = fmaxf(swmax, fabsf(spq));
            if (fabsf(spq) > skipthr) {
                float dpp = nrm[p], dqq = nrm[q];    // broadcast LDS per quarter
                float tau = (dqq - dpp) / (2.f * spq);
                float tt = copysignf(1.f, tau) / (fabsf(tau) + sqrtf(1.f + tau * tau));
                float c = rsqrtf(1.f + tt * tt);
                float s = tt * c;
                ull c2 = f2pack(c, c), s2 = f2pack(s, s), ns2 = f2pack(-s, -s);
                ulonglong2 N0, N1, M0, M1;
                N0.x = f2fma(A0.x, c2, f2mul(B0.x, ns2));
                N0.y = f2fma(A0.y, c2, f2mul(B0.y, ns2));
                N1.x = f2fma(A1.x, c2, f2mul(B1.x, ns2));
                N1.y = f2fma(A1.y, c2, f2mul(B1.y, ns2));
                M0.x = f2fma(A0.x, s2, f2mul(B0.x, c2));
                M0.y = f2fma(A0.y, s2, f2mul(B0.y, c2));
                M1.x = f2fma(A1.x, s2, f2mul(B1.x, c2));
                M1.y = f2fma(A1.y, s2, f2mul(B1.y, c2));
                Up[ql] = N0; Up[ql + 8] = N1;
                Uq[ql] = M0; Uq[ql + 8] = M1;
                if (ql == 0) {                       // lanes 0,8,16,24
                    float cc = c * c, ss = s * s, cs2 = 2.f * c * s * spq;
                    nrm[p] = cc * dpp + ss * dqq - cs2;
                    nrm[q] = ss * dpp + cc * dqq + cs2;
                }
            }
            __syncthreads();
        }
        // merge quarters' swmax, then block-reduce
        swmax = fmaxf(swmax, __shfl_xor_sync(0xffffffffu, swmax, 8));
        swmax = fmaxf(swmax, __shfl_xor_sync(0xffffffffu, swmax, 16));
        if (lane == 0) wred[warp] = swmax;
        __syncthreads();
        if (t == 0) {
            float m = wred[0];
            for (int i = 1; i < 8; ++i) m = fmaxf(m, wred[i]);
            conv_s = (m < convthr) ? 1 : 0;
        }
        __syncthreads();
        if (conv_s) break;
    }

    // exact column norms (double), lambda = ||u|| - sigma, scale g = f/||u||^2
    if (t < 64) {
        const float* uc = U + t * UPAD;
        double s = 0.0;
        #pragma unroll 8
        for (int r_ = 0; r_ < 64; ++r_) { double v = (double)uc[r_]; s += v * v; }
        double rho = sqrt(s);
        float lam = (float)(rho - (double)sigma);
        float f = logf(fmaxf(lam, 1e-4f));
        gsc[t] = (float)((double)f / s);
    }
    __syncthreads();

    // L[i][j] = sum_m gsc[m] * U[m][i] * U[m][j]; thread: row i0 x 16-col chunk
    const int i0 = t >> 2;
    const int j0 = (t & 3) << 4;
    float acc16[16];
    #pragma unroll
    for (int jj = 0; jj < 16; ++jj) acc16[jj] = 0.f;
    #pragma unroll 4
    for (int m = 0; m < 64; ++m) {
        float a = gsc[m] * U[m * UPAD + i0];
        const float* ur = U + m * UPAD + j0;
        #pragma unroll
        for (int jj = 0; jj < 16; ++jj) acc16[jj] += a * ur[jj];
    }
    float lsum = 0.f, lsq = 0.f;
    float* dst = g_lbuf + (size_t)b * 4096;
    #pragma unroll
    for (int jj = 0; jj < 16; ++jj) {
        float v = acc16[jj];
        dst[i0 * 64 + j0 + jj] = v;
        lsum += v; lsq += v * v;
    }
    #pragma unroll
    for (int off = 16; off; off >>= 1) {
        lsum += __shfl_down_sync(0xffffffffu, lsum, off);
        lsq  += __shfl_down_sync(0xffffffffu, lsq, off);
    }
    if (lane == 0) { wred[warp] = lsum; wred[8 + warp] = lsq; }
    __syncthreads();
    if (t == 0) {
        float s1 = 0.f, s2 = 0.f;
        for (int i = 0; i < 8; ++i) { s1 += wred[i]; s2 += wred[8 + i]; }
        g_eusum[b] = s1;
        g_eusq[b]  = s2;
    }
}

// ---------------- K2: block 1  (matnorm(eu) @ w2 -> relu -> @w3 + eu) ----------------
__global__ __launch_bounds__(128) void dense1_kernel(const float* __restrict__ w2, const float* __restrict__ b2,
                                                     const float* __restrict__ w3, const float* __restrict__ b3) {
    const int t = threadIdx.x;
    const int n = blockIdx.y;
    const int pos = blockIdx.x * 128 + t;
    __shared__ float sw2[1024], sw3[1024], sb2[32], sb3[32];
    __shared__ float meanS[22], isdS[22], em3S[10];
    __shared__ float acc1[32], acc2[32];
    for (int i = t; i < 1024; i += 128) { sw2[i] = w2[i]; sw3[i] = w3[i]; }
    if (t < 32) { sb2[t] = b2[t]; sb3[t] = b3[t]; acc1[t] = 0.f; acc2[t] = 0.f; }
    if (t < 22) {
        float mu = g_eusum[n * 22 + t] * (1.f / 4096.f);
        float var = fmaxf(g_eusq[n * 22 + t] * (1.f / 4096.f) - mu * mu, 0.f);
        meanS[t] = mu;
        isdS[t] = 1.f / fmaxf(sqrtf(var), 1e-3f);   // matnorm: clamp OUTSIDE sqrt
    }
    if (t < 10) em3S[t] = g_em3[t];
    __syncthreads();

    float eu[32];
    #pragma unroll
    for (int c = 0; c < 22; ++c) eu[c] = g_lbuf[((size_t)n * 22 + c) * 4096 + pos];
    #pragma unroll
    for (int c = 22; c < 32; ++c) eu[c] = em3S[c - 22];
    float mt[22];
    #pragma unroll
    for (int c = 0; c < 22; ++c) mt[c] = (eu[c] - meanS[c]) * isdS[c];
    // matnorm of the constant embedding channels is exactly 0 (std clamped), so skip c>=22
    float res[32];
    #pragma unroll
    for (int o = 0; o < 32; ++o) {
        float a = sb2[o];
        #pragma unroll
        for (int c = 0; c < 22; ++c) a += mt[c] * sw2[c * 32 + o];
        res[o] = fmaxf(a, 0.f);
    }
    #pragma unroll
    for (int o = 0; o < 32; ++o) {
        float a = sb3[o];
        #pragma unroll
        for (int c = 0; c < 32; ++c) a += res[c] * sw3[c * 32 + o];
        float h = eu[o] + a;
        g_h2[((size_t)n * 32 + o) * 4096 + pos] = h;
        float s1 = h, s2 = h * h;
        #pragma unroll
        for (int off = 16; off; off >>= 1) {
            s1 += __shfl_down_sync(0xffffffffu, s1, off);
            s2 += __shfl_down_sync(0xffffffffu, s2, off);
        }
        if ((t & 31) == 0) { atomicAdd(&acc1[o], s1); atomicAdd(&acc2[o], s2); }
    }
    __syncthreads();
    if (t < 32) {
        atomicAdd(&g_h2sum[n * 32 + t], acc1[t]);
        atomicAdd(&g_h2sq[n * 32 + t], acc2[t]);
    }
}

// ---------------- K3: block 2  (matnorm(h2) @ w4 -> relu -> @w5 + h2, mean) ----------------
__global__ __launch_bounds__(128) void dense2_kernel(const float* __restrict__ w4, const float* __restrict__ b4,
                                                     const float* __restrict__ w5, const float* __restrict__ b5) {
    const int t = threadIdx.x;
    const int n = blockIdx.y;
    const int pos = blockIdx.x * 128 + t;
    __shared__ float sw4[1024], sw5[1024], sb4[32], sb5[32];
    __shared__ float meanS[32], isdS[32];
    __shared__ float acc1[32];
    for (int i = t; i < 1024; i += 128) { sw4[i] = w4[i]; sw5[i] = w5[i]; }
    if (t < 32) {
        sb4[t] = b4[t]; sb5[t] = b5[t]; acc1[t] = 0.f;
        float mu = g_h2sum[n * 32 + t] * (1.f / 4096.f);
        float var = fmaxf(g_h2sq[n * 32 + t] * (1.f / 4096.f) - mu * mu, 0.f);
        meanS[t] = mu;
        isdS[t] = 1.f / fmaxf(sqrtf(var), 1e-3f);
    }
    __syncthreads();

    float hv[32];
    #pragma unroll
    for (int c = 0; c < 32; ++c) hv[c] = g_h2[((size_t)n * 32 + c) * 4096 + pos];
    float mt[32];
    #pragma unroll
    for (int c = 0; c < 32; ++c) mt[c] = (hv[c] - meanS[c]) * isdS[c];
    float res[32];
    #pragma unroll
    for (int o = 0; o < 32; ++o) {
        float a = sb4[o];
        #pragma unroll
        for (int c = 0; c < 32; ++c) a += mt[c] * sw4[c * 32 + o];
        res[o] = fmaxf(a, 0.f);
    }
    #pragma unroll
    for (int o = 0; o < 32; ++o) {
        float a = sb5[o];
        #pragma unroll
        for (int c = 0; c < 32; ++c) a += res[c] * sw5[c * 32 + o];
        float h = hv[o] + a;
        float s1 = h;
        #pragma unroll
        for (int off = 16; off; off >>= 1) s1 += __shfl_down_sync(0xffffffffu, s1, off);
        if ((t & 31) == 0) atomicAdd(&acc1[o], s1);
    }
    __syncthreads();
    if (t < 32) atomicAdd(&g_cov3[n * 32 + t], acc1[t]);
}

// ---------------- K4: head (cov3 @ w -> softmax) ----------------
__global__ void head_kernel(const float* __restrict__ w, float* __restrict__ out) {
    const int n = threadIdx.x;  // 256 threads
    float c[32];
    #pragma unroll
    for (int ch = 0; ch < 32; ++ch) c[ch] = g_cov3[n * 32 + ch] * (1.f / 4096.f);
    float lg[7];
    #pragma unroll
    for (int cls = 0; cls < 7; ++cls) {
        float a = 0.f;
        #pragma unroll
        for (int ch = 0; ch < 32; ++ch) a += c[ch] * w[ch * 7 + cls];
        lg[cls] = a;
    }
    float mx = lg[0];
    #pragma unroll
    for (int cls = 1; cls < 7; ++cls) mx = fmaxf(mx, lg[cls]);
    float sum = 0.f;
    #pragma unroll
    for (int cls = 0; cls < 7; ++cls) { lg[cls] = expf(lg[cls] - mx); sum += lg[cls]; }
    float inv = 1.f / sum;
    #pragma unroll
    for (int cls = 0; cls < 7; ++cls) out[n * 7 + cls] = lg[cls] * inv;
}

// ---------------- launch ----------------
extern "C" void kernel_launch(void* const* d_in, const int* in_sizes, int n_in,
                              void* d_out, int out_size) {
    const float* x   = (const float*)d_in[0];
    const void*  M   = d_in[1];
    const float* w   = (const float*)d_in[2];
    const float* w2  = (const float*)d_in[3];
    const float* b2  = (const float*)d_in[4];
    const float* w3  = (const float*)d_in[5];
    const float* b3  = (const float*)d_in[6];
    const float* w4  = (const float*)d_in[7];
    const float* b4  = (const float*)d_in[8];
    const float* w5  = (const float*)d_in[9];
    const float* b5  = (const float*)d_in[10];
    const float* we1 = (const float*)d_in[11];
    const float* be1 = (const float*)d_in[12];
    const float* we2 = (const float*)d_in[13];
    const float* be2 = (const float*)d_in[14];
    const float* we3 = (const float*)d_in[15];
    const float* be3 = (const float*)d_in[16];
    const float* lng = (const float*)d_in[17];
    const float* lnb = (const float*)d_in[18];

    init_kernel<<<1, 256>>>(M, we1, be1, we2, be2, we3, be3, lng, lnb);
    eig_kernel<<<256 * 22, 256>>>(x);
    dense1_kernel<<<dim3(32, 256), 128>>>(w2, b2, w3, b3);
    dense2_kernel<<<dim3(32, 256), 128>>>(w4, b4, w5, b5);
    head_kernel<<<1, 256>>>(w, (float*)d_out);
}